// round 1
// baseline (speedup 1.0000x reference)
#include <cuda_runtime.h>
#include <math.h>

#define IMW 1024
#define IMH 1024
#define NB  16
#define NPIX (NB * IMH * IMW)          // 16,777,216
#define GRIDX (IMW / 32)               // 32
#define GRIDY (IMH / 32)               // 32
#define NBLK  (NB * GRIDX * GRIDY)     // 16384

struct Ctrl {
    unsigned long long iterSum;        // packed: predSum (lo 32) | targetSum (hi 32)
    unsigned int cur;                  // which buffer holds current skel (0=A,1=B)
    unsigned int doneP, doneT, allDone;
    unsigned int prevValidP, prevValidT;
    unsigned int prevP, prevT;
};

__device__ Ctrl g_ctrl;
__device__ unsigned short g_binit[NPIX];   // packed initial binaries (pred lo byte, target hi byte)
__device__ unsigned short g_bufA[NPIX];    // skeleton ping
__device__ unsigned short g_bufB[NPIX];    // skeleton pong
__device__ double g_part0[NBLK * 6];       // sum_p, sum_t, sum_pt, focal, conn_num, n_water
__device__ double g_part1[NBLK * 3];       // sumPskel, sumTskel, inter_s

__device__ __forceinline__ double warp_sum_d(double v) {
#pragma unroll
    for (int o = 16; o > 0; o >>= 1) v += __shfl_down_sync(0xffffffffu, v, o);
    return v;
}
__device__ __forceinline__ unsigned warp_sum_u(unsigned v) {
#pragma unroll
    for (int o = 16; o > 0; o >>= 1) v += __shfl_down_sync(0xffffffffu, v, o);
    return v;
}

__global__ void k_reset() {
    g_ctrl.iterSum = 0ull;
    g_ctrl.cur = 0u;
    g_ctrl.doneP = 0u; g_ctrl.doneT = 0u; g_ctrl.allDone = 0u;
    g_ctrl.prevValidP = 0u; g_ctrl.prevValidT = 0u;
    g_ctrl.prevP = 0u; g_ctrl.prevT = 0u;
}

// ---------------------------------------------------------------------------
// K_init: sigmoid, binarize, dice/focal pointwise sums, connectivity box-conv,
// write packed binaries (binit + bufA).
// Block (32,8), tile 32x32 (4 rows per thread). Grid (32,32,16).
// ---------------------------------------------------------------------------
__global__ void k_init(const float* __restrict__ pred, const float* __restrict__ target) {
    __shared__ float sp[34][34];
    __shared__ float st[34][34];

    const int gx0 = blockIdx.x * 32 - 1;
    const int gy0 = blockIdx.y * 32 - 1;
    const size_t ib = (size_t)blockIdx.z * (size_t)(IMH * IMW);
    const int tid = threadIdx.y * 32 + threadIdx.x;

    for (int idx = tid; idx < 34 * 34; idx += 256) {
        int ly = idx / 34, lx = idx - ly * 34;
        int gy = gy0 + ly, gx = gx0 + lx;
        float pv = 0.f, tv = 0.f;
        if ((unsigned)gy < (unsigned)IMH && (unsigned)gx < (unsigned)IMW) {
            size_t g = ib + (size_t)gy * IMW + (size_t)gx;
            float x = pred[g];
            pv = 1.0f / (1.0f + expf(-x));   // sigmoid
            tv = target[g];
        }
        sp[ly][lx] = pv;
        st[ly][lx] = tv;
    }
    __syncthreads();

    double a_sum_p = 0, a_sum_t = 0, a_sum_pt = 0, a_focal = 0, a_conn = 0, a_nw = 0;
    const int lx = threadIdx.x;

#pragma unroll
    for (int r = 0; r < 4; r++) {
        int ly = threadIdx.y + 8 * r;
        float p = sp[ly + 1][lx + 1];
        float t = st[ly + 1][lx + 1];

        a_sum_p += (double)p;
        a_sum_t += (double)t;
        a_sum_pt += (double)(p * t);

        // focal term (target is exactly 0.0 or 1.0)
        float pc = fminf(fmaxf(p, 1e-6f), 1.0f - 1e-6f);
        float term = (t > 0.5f)
            ? 0.25f * (1.0f - pc) * (1.0f - pc) * (-logf(pc))
            : 0.75f * pc * pc * (-logf(1.0f - pc));
        a_focal += (double)term;

        // connectivity: 3x3 box sums
        float ps9 = 0.f, ts9 = 0.f;
#pragma unroll
        for (int dy = 0; dy < 3; dy++)
#pragma unroll
            for (int dx = 0; dx < 3; dx++) {
                ps9 += sp[ly + dy][lx + dx];
                ts9 += st[ly + dy][lx + dx];
            }
        if (t > 0.5f) {
            float d = (ps9 - ts9) * (1.0f / 9.0f);
            a_conn += (double)(d * d);
            a_nw += 1.0;
        }

        unsigned bp = (p > 0.5f) ? 1u : 0u;
        unsigned bt = (t > 0.5f) ? 1u : 0u;
        unsigned short pk = (unsigned short)(bp | (bt << 8));
        int gy = blockIdx.y * 32 + ly;
        int gxp = blockIdx.x * 32 + lx;
        size_t g = ib + (size_t)gy * IMW + (size_t)gxp;
        g_binit[g] = pk;
        g_bufA[g] = pk;
    }

    // block reduce 6 doubles -> partials (deterministic: per-block slot)
    __shared__ double red[8][6];
    double vals[6] = { a_sum_p, a_sum_t, a_sum_pt, a_focal, a_conn, a_nw };
    int lane = tid & 31, wid = tid >> 5;
#pragma unroll
    for (int k = 0; k < 6; k++) {
        double v = warp_sum_d(vals[k]);
        if (lane == 0) red[wid][k] = v;
    }
    __syncthreads();
    if (tid == 0) {
        int bid = ((int)blockIdx.z * GRIDY + (int)blockIdx.y) * GRIDX + (int)blockIdx.x;
#pragma unroll
        for (int k = 0; k < 6; k++) {
            double s = 0;
            for (int w2 = 0; w2 < 8; w2++) s += red[w2][k];
            g_part0[bid * 6 + k] = s;
        }
    }
}

// ---------------------------------------------------------------------------
// K_iter: one skeleton iteration on packed u16 (both masks at once).
// eroded = (3x3 sum >= 9); new = (v<=eroded ? v : 0) + eroded. Values in {0,1,2}.
// Accumulates exact integer sums of the written skeleton (packed u64 atomic).
// ---------------------------------------------------------------------------
__global__ void k_iter() {
    if (g_ctrl.allDone) return;
    const unsigned cur = g_ctrl.cur;
    const unsigned doneP = g_ctrl.doneP;
    const unsigned doneT = g_ctrl.doneT;
    const unsigned short* __restrict__ in = cur ? g_bufB : g_bufA;
    unsigned short* __restrict__ out = cur ? g_bufA : g_bufB;

    __shared__ unsigned short s[34][34];
    const int gx0 = blockIdx.x * 32 - 1;
    const int gy0 = blockIdx.y * 32 - 1;
    const size_t ib = (size_t)blockIdx.z * (size_t)(IMH * IMW);
    const int tid = threadIdx.y * 32 + threadIdx.x;

    for (int idx = tid; idx < 34 * 34; idx += 256) {
        int ly = idx / 34, lx = idx - ly * 34;
        int gy = gy0 + ly, gx = gx0 + lx;
        unsigned short v = 0;
        if ((unsigned)gy < (unsigned)IMH && (unsigned)gx < (unsigned)IMW)
            v = in[ib + (size_t)gy * IMW + (size_t)gx];
        s[ly][lx] = v;
    }
    __syncthreads();

    unsigned sumP = 0, sumT = 0;
    const int lx = threadIdx.x;
#pragma unroll
    for (int r = 0; r < 4; r++) {
        int ly = threadIdx.y + 8 * r;
        unsigned v = s[ly + 1][lx + 1];
        unsigned ns = 0;
#pragma unroll
        for (int dy = 0; dy < 3; dy++)
#pragma unroll
            for (int dx = 0; dx < 3; dx++) ns += (unsigned)s[ly + dy][lx + dx];

        unsigned s9P = ns & 0xffu;
        unsigned s9T = (ns >> 8) & 0xffu;
        unsigned vP = v & 0xffu;
        unsigned vT = v >> 8;
        unsigned eP = (s9P >= 9u) ? 1u : 0u;
        unsigned eT = (s9T >= 9u) ? 1u : 0u;
        unsigned nP = ((vP <= eP) ? vP : 0u) + eP;
        unsigned nT = ((vT <= eT) ? vT : 0u) + eT;
        unsigned oP = doneP ? vP : nP;
        unsigned oT = doneT ? vT : nT;

        int gy = blockIdx.y * 32 + ly;
        int gxp = blockIdx.x * 32 + lx;
        out[ib + (size_t)gy * IMW + (size_t)gxp] = (unsigned short)(oP | (oT << 8));
        sumP += oP;
        sumT += oT;
    }

    __shared__ unsigned redP[8], redT[8];
    int lane = tid & 31, wid = tid >> 5;
    unsigned wp = warp_sum_u(sumP);
    unsigned wt = warp_sum_u(sumT);
    if (lane == 0) { redP[wid] = wp; redT[wid] = wt; }
    __syncthreads();
    if (tid == 0) {
        unsigned sP = 0, sT = 0;
        for (int w2 = 0; w2 < 8; w2++) { sP += redP[w2]; sT += redT[w2]; }
        atomicAdd(&g_ctrl.iterSum, (unsigned long long)sP | ((unsigned long long)sT << 32));
    }
}

// ---------------------------------------------------------------------------
// K_ctrl: 1-thread convergence/bookkeeping. Sums are exact integers, so the
// |curr - prev| < 1 check is integer equality (matches JAX float32 exactly
// because every partial sum is an integer < 2^24).
// ---------------------------------------------------------------------------
__global__ void k_ctrl() {
    if (g_ctrl.allDone) return;
    unsigned long long s = g_ctrl.iterSum;
    unsigned cP = (unsigned)(s & 0xffffffffull);
    unsigned cT = (unsigned)(s >> 32);
    if (!g_ctrl.doneP) {
        if (g_ctrl.prevValidP && cP == g_ctrl.prevP) g_ctrl.doneP = 1u;
        g_ctrl.prevP = cP;
        g_ctrl.prevValidP = 1u;
    }
    if (!g_ctrl.doneT) {
        if (g_ctrl.prevValidT && cT == g_ctrl.prevT) g_ctrl.doneT = 1u;
        g_ctrl.prevT = cT;
        g_ctrl.prevValidT = 1u;
    }
    g_ctrl.iterSum = 0ull;
    g_ctrl.cur ^= 1u;   // cur now points at the buffer just written
    if (g_ctrl.doneP && g_ctrl.doneT) g_ctrl.allDone = 1u;
}

// ---------------------------------------------------------------------------
// K_final: sobel edges from initial binaries (halo stencil) + clip with final
// skeleton; accumulate skeleton-dice sums.
// ---------------------------------------------------------------------------
__global__ void k_final() {
    __shared__ unsigned short s[34][34];
    const int gx0 = blockIdx.x * 32 - 1;
    const int gy0 = blockIdx.y * 32 - 1;
    const size_t ib = (size_t)blockIdx.z * (size_t)(IMH * IMW);
    const int tid = threadIdx.y * 32 + threadIdx.x;

    for (int idx = tid; idx < 34 * 34; idx += 256) {
        int ly = idx / 34, lx = idx - ly * 34;
        int gy = gy0 + ly, gx = gx0 + lx;
        unsigned short v = 0;
        if ((unsigned)gy < (unsigned)IMH && (unsigned)gx < (unsigned)IMW)
            v = g_binit[ib + (size_t)gy * IMW + (size_t)gx];
        s[ly][lx] = v;
    }
    __syncthreads();

    const unsigned short* __restrict__ skel = g_ctrl.cur ? g_bufB : g_bufA;

    double aPs = 0, aTs = 0, aI = 0;
    const int lx = threadIdx.x;
#pragma unroll
    for (int r = 0; r < 4; r++) {
        int ly = threadIdx.y + 8 * r;
        // packed sobel: each field value <=1, weighted sums <=4 per byte -> no carry
        unsigned posx = (unsigned)s[ly][lx + 2] + 2u * (unsigned)s[ly + 1][lx + 2] + (unsigned)s[ly + 2][lx + 2];
        unsigned negx = (unsigned)s[ly][lx]     + 2u * (unsigned)s[ly + 1][lx]     + (unsigned)s[ly + 2][lx];
        unsigned posy = (unsigned)s[ly + 2][lx] + 2u * (unsigned)s[ly + 2][lx + 1] + (unsigned)s[ly + 2][lx + 2];
        unsigned negy = (unsigned)s[ly][lx]     + 2u * (unsigned)s[ly][lx + 1]     + (unsigned)s[ly][lx + 2];

        int gxP = (int)(posx & 0xffu) - (int)(negx & 0xffu);
        int gyP = (int)(posy & 0xffu) - (int)(negy & 0xffu);
        int gxT = (int)((posx >> 8) & 0xffu) - (int)((negx >> 8) & 0xffu);
        int gyT = (int)((posy >> 8) & 0xffu) - (int)((negy >> 8) & 0xffu);

        float eP = sqrtf((float)(gxP * gxP + gyP * gyP) + 1e-8f);
        float eT = sqrtf((float)(gxT * gxT + gyT * gyT) + 1e-8f);

        int gy = blockIdx.y * 32 + ly;
        int gxp = blockIdx.x * 32 + lx;
        unsigned sv = skel[ib + (size_t)gy * IMW + (size_t)gxp];
        float skP = fminf((float)(sv & 0xffu) + 0.5f * eP, 1.0f);
        float skT = fminf((float)(sv >> 8) + 0.5f * eT, 1.0f);

        aPs += (double)skP;
        aTs += (double)skT;
        aI += (double)(skP * skT);
    }

    __shared__ double red[8][3];
    double vals[3] = { aPs, aTs, aI };
    int lane = tid & 31, wid = tid >> 5;
#pragma unroll
    for (int k = 0; k < 3; k++) {
        double v = warp_sum_d(vals[k]);
        if (lane == 0) red[wid][k] = v;
    }
    __syncthreads();
    if (tid == 0) {
        int bid = ((int)blockIdx.z * GRIDY + (int)blockIdx.y) * GRIDX + (int)blockIdx.x;
#pragma unroll
        for (int k = 0; k < 3; k++) {
            double sum = 0;
            for (int w2 = 0; w2 < 8; w2++) sum += red[w2][k];
            g_part1[bid * 3 + k] = sum;
        }
    }
}

// ---------------------------------------------------------------------------
// K_finish: deterministic fixed-order reduction of partials + loss combine.
// ---------------------------------------------------------------------------
__global__ void k_finish(float* __restrict__ out, int out_size) {
    const int tid = threadIdx.x;  // 256 threads
    double acc[9];
#pragma unroll
    for (int k = 0; k < 9; k++) acc[k] = 0.0;

    for (int i = tid; i < NBLK; i += 256) {
#pragma unroll
        for (int k = 0; k < 6; k++) acc[k] += g_part0[i * 6 + k];
#pragma unroll
        for (int k = 0; k < 3; k++) acc[6 + k] += g_part1[i * 3 + k];
    }

    __shared__ double red[8][9];
    int lane = tid & 31, wid = tid >> 5;
#pragma unroll
    for (int k = 0; k < 9; k++) {
        double v = warp_sum_d(acc[k]);
        if (lane == 0) red[wid][k] = v;
    }
    __syncthreads();
    if (tid == 0) {
        double A[9];
#pragma unroll
        for (int k = 0; k < 9; k++) {
            double s = 0;
            for (int w2 = 0; w2 < 8; w2++) s += red[w2][k];
            A[k] = s;
        }
        double sum_p = A[0], sum_t = A[1], sum_pt = A[2];
        double focal_sum = A[3], conn_num = A[4], nw = A[5];
        double sPs = A[6], sTs = A[7], inter_s = A[8];

        double skeleton = 1.0 - (2.0 * inter_s + 1.0) / (sPs + sTs + 1.0);
        double dice = 1.0 - (2.0 * sum_pt + 1.0) / (sum_p + sum_t + 1.0);
        double focal = focal_sum / (double)NPIX;
        focal = fmin(fmax(focal, 0.0), 10.0);
        double conn = (nw == 0.0) ? 0.0 : conn_num / fmax(nw, 1.0);

        double total = 0.3 * skeleton + 0.4 * dice + 0.2 * focal + 0.1 * conn;
        if (isnan(total) || isinf(total)) total = dice;

        float f = (float)total;
        for (int j = 0; j < out_size; j++) out[j] = f;
    }
}

extern "C" void kernel_launch(void* const* d_in, const int* in_sizes, int n_in,
                              void* d_out, int out_size) {
    (void)in_sizes; (void)n_in;
    const float* pred = (const float*)d_in[0];
    const float* target = (const float*)d_in[1];
    float* out = (float*)d_out;

    dim3 blk(32, 8);
    dim3 grd(GRIDX, GRIDY, NB);

    k_reset<<<1, 1>>>();
    k_init<<<grd, blk>>>(pred, target);
    for (int i = 0; i < 10; i++) {
        k_iter<<<grd, blk>>>();
        k_ctrl<<<1, 1>>>();
    }
    k_final<<<grd, blk>>>();
    k_finish<<<1, 256>>>(out, out_size);
}

// round 2
// speedup vs baseline: 2.2368x; 2.2368x over previous
#include <cuda_runtime.h>
#include <math.h>

#define IMW 1024
#define IMH 1024
#define NB  16
#define NPIX (NB * IMH * IMW)          // 16,777,216
#define WPR  (IMW / 32)                // 32 words per row
#define NWPI (IMH * WPR)               // 32768 words per image
#define NW   (NB * NWPI)               // 524,288 words per mask
#define GRIDX (IMW / 32)
#define GRIDY (IMH / 32)
#define NBLK0 (NB * GRIDX * GRIDY)     // 16384 init blocks
#define FBLK  (NW / 256)               // 2048 final blocks

// bitmaps: [mask(0=pred,1=target)][iteration 0..10][word]
__device__ unsigned g_bm[2][11][NW];
__device__ unsigned g_psum[22];          // popcounts per mask/iter
__device__ double g_part0[NBLK0 * 6];    // sum_p, sum_t, sum_pt, focal, conn, n_water
__device__ double g_part1[FBLK * 3];     // sumPskel, sumTskel, inter_s

__device__ __forceinline__ double warp_sum_d(double v) {
#pragma unroll
    for (int o = 16; o > 0; o >>= 1) v += __shfl_down_sync(0xffffffffu, v, o);
    return v;
}
__device__ __forceinline__ unsigned warp_sum_u(unsigned v) {
#pragma unroll
    for (int o = 16; o > 0; o >>= 1) v += __shfl_down_sync(0xffffffffu, v, o);
    return v;
}

// ---------------------------------------------------------------------------
// k_init: sigmoid, pointwise losses (float accumulators), connectivity 3x3,
// emit 1-bit binary masks via ballot. Also zeroes g_psum (block 0).
// Block (32,8), tile 32x32 (4 rows/thread). Grid (32,32,16).
// ---------------------------------------------------------------------------
__global__ void k_init(const float* __restrict__ pred, const float* __restrict__ target) {
    __shared__ float sp[34][34];
    __shared__ float st[34][34];

    const int gx0 = blockIdx.x * 32 - 1;
    const int gy0 = blockIdx.y * 32 - 1;
    const size_t ib = (size_t)blockIdx.z * (size_t)(IMH * IMW);
    const int tid = threadIdx.y * 32 + threadIdx.x;

    if (blockIdx.x == 0 && blockIdx.y == 0 && blockIdx.z == 0 && tid < 22)
        g_psum[tid] = 0u;

    for (int idx = tid; idx < 34 * 34; idx += 256) {
        int ly = idx / 34, lx = idx - ly * 34;
        int gy = gy0 + ly, gx = gx0 + lx;
        float pv = 0.f, tv = 0.f;
        if ((unsigned)gy < (unsigned)IMH && (unsigned)gx < (unsigned)IMW) {
            size_t g = ib + (size_t)gy * IMW + (size_t)gx;
            float x = pred[g];
            pv = 1.0f / (1.0f + expf(-x));
            tv = target[g];
        }
        sp[ly][lx] = pv;
        st[ly][lx] = tv;
    }
    __syncthreads();

    float a_sum_p = 0.f, a_sum_t = 0.f, a_sum_pt = 0.f, a_focal = 0.f, a_conn = 0.f, a_nw = 0.f;
    const int lx = threadIdx.x;

#pragma unroll
    for (int r = 0; r < 4; r++) {
        int ly = threadIdx.y + 8 * r;
        float p = sp[ly + 1][lx + 1];
        float t = st[ly + 1][lx + 1];

        a_sum_p += p;
        a_sum_t += t;
        a_sum_pt += p * t;

        float pc = fminf(fmaxf(p, 1e-6f), 1.0f - 1e-6f);
        float term = (t > 0.5f)
            ? 0.25f * (1.0f - pc) * (1.0f - pc) * (-logf(pc))
            : 0.75f * pc * pc * (-logf(1.0f - pc));
        a_focal += term;

        float ps9 = 0.f, ts9 = 0.f;
#pragma unroll
        for (int dy = 0; dy < 3; dy++)
#pragma unroll
            for (int dx = 0; dx < 3; dx++) {
                ps9 += sp[ly + dy][lx + dx];
                ts9 += st[ly + dy][lx + dx];
            }
        if (t > 0.5f) {
            float d = (ps9 - ts9) * (1.0f / 9.0f);
            a_conn += d * d;
            a_nw += 1.0f;
        }

        unsigned bp = __ballot_sync(0xffffffffu, p > 0.5f);
        unsigned bt = __ballot_sync(0xffffffffu, t > 0.5f);
        if (lx == 0) {
            int gy = blockIdx.y * 32 + ly;
            int w = (int)blockIdx.z * NWPI + gy * WPR + (int)blockIdx.x;
            g_bm[0][0][w] = bp;
            g_bm[1][0][w] = bt;
        }
    }

    __shared__ double red[8][6];
    double vals[6] = { (double)a_sum_p, (double)a_sum_t, (double)a_sum_pt,
                       (double)a_focal, (double)a_conn, (double)a_nw };
    int lane = tid & 31, wid = tid >> 5;
#pragma unroll
    for (int k = 0; k < 6; k++) {
        double v = warp_sum_d(vals[k]);
        if (lane == 0) red[wid][k] = v;
    }
    __syncthreads();
    if (tid == 0) {
        int bid = ((int)blockIdx.z * GRIDY + (int)blockIdx.y) * GRIDX + (int)blockIdx.x;
#pragma unroll
        for (int k = 0; k < 6; k++) {
            double s = 0;
            for (int w2 = 0; w2 < 8; w2++) s += red[w2][k];
            g_part0[bid * 6 + k] = s;
        }
    }
}

// ---------------------------------------------------------------------------
// k_iter(i): bitmap skeleton step for both masks, state i-1 -> state i.
//   i odd : out = erode9(b)  (state scale becomes 2)
//   i even: out = (3x3 popcount >= 5)  (state scale becomes 1)
// Each thread processes 4 consecutive words (128 px of one row).
// Accumulates exact popcounts into g_psum[mask*11 + i].
// ---------------------------------------------------------------------------
__global__ void k_iter(int iter) {
    const int t4 = blockIdx.x * blockDim.x + threadIdx.x;  // 0..NW/4-1
    const int w0 = t4 * 4;
    const int img = w0 >> 15;
    const int row = (w0 >> 5) & 1023;
    const int cb = w0 & 31;  // 0,4,...,28
    const size_t base = (size_t)img * NWPI + (size_t)row * WPR;
    const bool odd = (iter & 1) != 0;

    unsigned popm[2];
#pragma unroll
    for (int m = 0; m < 2; m++) {
        const unsigned* __restrict__ in = g_bm[m][iter - 1];
        unsigned* __restrict__ out = g_bm[m][iter];

        unsigned u[6], md[6], d[6];
#pragma unroll
        for (int i = 0; i < 6; i++) {
            int c = cb - 1 + i;
            bool cok = (unsigned)c < 32u;
            u[i]  = (cok && row > 0)    ? in[base - WPR + c] : 0u;
            md[i] = (cok)               ? in[base + c]       : 0u;
            d[i]  = (cok && row < 1023) ? in[base + WPR + c] : 0u;
        }

        unsigned pop = 0;
        if (odd) {
            unsigned va[6];
#pragma unroll
            for (int i = 0; i < 6; i++) va[i] = u[i] & md[i] & d[i];
#pragma unroll
            for (int j = 0; j < 4; j++) {
                unsigned c = va[j + 1];
                unsigned o = c & ((c << 1) | (va[j] >> 31)) & ((c >> 1) | (va[j + 2] << 31));
                out[base + cb + j] = o;
                pop += __popc(o);
            }
        } else {
            unsigned s0[6], s1[6];
#pragma unroll
            for (int i = 0; i < 6; i++) {
                s0[i] = u[i] ^ md[i] ^ d[i];
                s1[i] = (u[i] & md[i]) | (d[i] & (u[i] | md[i]));
            }
#pragma unroll
            for (int j = 0; j < 4; j++) {
                unsigned c0 = s0[j + 1], c1 = s1[j + 1];
                unsigned w0b = (c0 << 1) | (s0[j] >> 31);
                unsigned w1b = (c1 << 1) | (s1[j] >> 31);
                unsigned e0 = (c0 >> 1) | (s0[j + 2] << 31);
                unsigned e1 = (c1 >> 1) | (s1[j + 2] << 31);
                // (w1b w0b) + (c1 c0)
                unsigned t0 = w0b ^ c0, car0 = w0b & c0;
                unsigned x = w1b ^ c1;
                unsigned t1 = x ^ car0;
                unsigned car1 = (w1b & c1) | (car0 & x);
                // + (e1 e0)
                unsigned u0 = t0 ^ e0, k0 = t0 & e0;
                unsigned y = t1 ^ e1;
                unsigned u1 = y ^ k0;
                unsigned k1 = (t1 & e1) | (k0 & y);
                unsigned u2 = car1 ^ k1;
                unsigned u3 = car1 & k1;
                unsigned o = u3 | (u2 & (u1 | u0));  // total >= 5
                out[base + cb + j] = o;
                pop += __popc(o);
            }
        }
        popm[m] = pop;
    }

    __shared__ unsigned red[2][8];
    int lane = threadIdx.x & 31, wid = threadIdx.x >> 5;
#pragma unroll
    for (int m = 0; m < 2; m++) {
        unsigned v = warp_sum_u(popm[m]);
        if (lane == 0) red[m][wid] = v;
    }
    __syncthreads();
    if (threadIdx.x == 0) {
#pragma unroll
        for (int m = 0; m < 2; m++) {
            unsigned s = 0;
            for (int w2 = 0; w2 < 8; w2++) s += red[m][w2];
            atomicAdd(&g_psum[m * 11 + iter], s);
        }
    }
}

// ---------------------------------------------------------------------------
// k_final: select converged snapshot per mask (redundant per-block scan of
// g_psum), Sobel-edge via 512-entry LUT on 9-bit neighborhoods of the initial
// binaries, combine with skeleton, accumulate skeleton-dice sums.
// One thread per 32-pixel word. Grid FBLK x 256.
// ---------------------------------------------------------------------------
__global__ void k_final() {
    __shared__ float lut[512];
    __shared__ int s_sel[2];
    const int tid = threadIdx.x;

    for (int i = tid; i < 512; i += 256) {
        int n0 = i & 1, n1 = (i >> 1) & 1, n2 = (i >> 2) & 1;
        int n3 = (i >> 3) & 1, n5 = (i >> 5) & 1;
        int n6 = (i >> 6) & 1, n7 = (i >> 7) & 1, n8 = (i >> 8) & 1;
        int gx = (n2 + 2 * n5 + n8) - (n0 + 2 * n3 + n6);
        int gy = (n6 + 2 * n7 + n8) - (n0 + 2 * n1 + n2);
        lut[i] = 0.5f * sqrtf((float)(gx * gx + gy * gy) + 1e-8f);
    }
    if (tid == 0) {
#pragma unroll
        for (int m = 0; m < 2; m++) {
            unsigned prev = g_psum[m * 11 + 1] << 1;  // sum_1 (scale 2)
            int sel = 10;
            for (int i = 2; i <= 10; i++) {
                unsigned cur = g_psum[m * 11 + i] << (i & 1);
                if (cur == prev) { sel = i; break; }
                prev = cur;
            }
            s_sel[m] = sel;
        }
    }
    __syncthreads();

    const int selP = s_sel[0], selT = s_sel[1];
    const float scP = (selP & 1) ? 2.0f : 1.0f;
    const float scT = (selT & 1) ? 2.0f : 1.0f;

    const int w = blockIdx.x * 256 + tid;
    const int img = w >> 15;
    const int row = (w >> 5) & 1023;
    const int col = w & 31;
    const size_t base = (size_t)img * NWPI + (size_t)row * WPR + col;
    const bool hasU = row > 0, hasD = row < 1023, hasL = col > 0, hasR = col < 31;

    unsigned long long e[2][3];
#pragma unroll
    for (int m = 0; m < 2; m++) {
        const unsigned* __restrict__ b = g_bm[m][0];
        unsigned U  = hasU ? b[base - WPR] : 0u;
        unsigned UL = (hasU && hasL) ? b[base - WPR - 1] : 0u;
        unsigned UR = (hasU && hasR) ? b[base - WPR + 1] : 0u;
        unsigned M  = b[base];
        unsigned L  = hasL ? b[base - 1] : 0u;
        unsigned R  = hasR ? b[base + 1] : 0u;
        unsigned D  = hasD ? b[base + WPR] : 0u;
        unsigned DL = (hasD && hasL) ? b[base + WPR - 1] : 0u;
        unsigned DR = (hasD && hasR) ? b[base + WPR + 1] : 0u;
        e[m][0] = ((unsigned long long)(UR & 1u) << 33) | ((unsigned long long)U << 1) | (UL >> 31);
        e[m][1] = ((unsigned long long)(R & 1u) << 33) | ((unsigned long long)M << 1) | (L >> 31);
        e[m][2] = ((unsigned long long)(DR & 1u) << 33) | ((unsigned long long)D << 1) | (DL >> 31);
    }
    const unsigned skP = g_bm[0][selP][base];
    const unsigned skT = g_bm[1][selT][base];

    float aPs = 0.f, aTs = 0.f, aI = 0.f;
#pragma unroll 8
    for (int k = 0; k < 32; k++) {
        unsigned idxP = ((unsigned)(e[0][0] >> k) & 7u) | (((unsigned)(e[0][1] >> k) & 7u) << 3)
                      | (((unsigned)(e[0][2] >> k) & 7u) << 6);
        unsigned idxT = ((unsigned)(e[1][0] >> k) & 7u) | (((unsigned)(e[1][1] >> k) & 7u) << 3)
                      | (((unsigned)(e[1][2] >> k) & 7u) << 6);
        float vP = fminf((((skP >> k) & 1u) ? scP : 0.f) + lut[idxP], 1.0f);
        float vT = fminf((((skT >> k) & 1u) ? scT : 0.f) + lut[idxT], 1.0f);
        aPs += vP;
        aTs += vT;
        aI += vP * vT;
    }

    __shared__ double red[8][3];
    double vals[3] = { (double)aPs, (double)aTs, (double)aI };
    int lane = tid & 31, wid = tid >> 5;
#pragma unroll
    for (int k = 0; k < 3; k++) {
        double v = warp_sum_d(vals[k]);
        if (lane == 0) red[wid][k] = v;
    }
    __syncthreads();
    if (tid == 0) {
#pragma unroll
        for (int k = 0; k < 3; k++) {
            double s = 0;
            for (int w2 = 0; w2 < 8; w2++) s += red[w2][k];
            g_part1[blockIdx.x * 3 + k] = s;
        }
    }
}

// ---------------------------------------------------------------------------
// k_finish: deterministic fixed-order reduction + loss combine.
// ---------------------------------------------------------------------------
__global__ void k_finish(float* __restrict__ out, int out_size) {
    const int tid = threadIdx.x;  // 256 threads
    double acc[9];
#pragma unroll
    for (int k = 0; k < 9; k++) acc[k] = 0.0;

    for (int i = tid; i < NBLK0; i += 256)
#pragma unroll
        for (int k = 0; k < 6; k++) acc[k] += g_part0[i * 6 + k];
    for (int i = tid; i < FBLK; i += 256)
#pragma unroll
        for (int k = 0; k < 3; k++) acc[6 + k] += g_part1[i * 3 + k];

    __shared__ double red[8][9];
    int lane = tid & 31, wid = tid >> 5;
#pragma unroll
    for (int k = 0; k < 9; k++) {
        double v = warp_sum_d(acc[k]);
        if (lane == 0) red[wid][k] = v;
    }
    __syncthreads();
    if (tid == 0) {
        double A[9];
#pragma unroll
        for (int k = 0; k < 9; k++) {
            double s = 0;
            for (int w2 = 0; w2 < 8; w2++) s += red[w2][k];
            A[k] = s;
        }
        double sum_p = A[0], sum_t = A[1], sum_pt = A[2];
        double focal_sum = A[3], conn_num = A[4], nw = A[5];
        double sPs = A[6], sTs = A[7], inter_s = A[8];

        double skeleton = 1.0 - (2.0 * inter_s + 1.0) / (sPs + sTs + 1.0);
        double dice = 1.0 - (2.0 * sum_pt + 1.0) / (sum_p + sum_t + 1.0);
        double focal = focal_sum / (double)NPIX;
        focal = fmin(fmax(focal, 0.0), 10.0);
        double conn = (nw == 0.0) ? 0.0 : conn_num / fmax(nw, 1.0);

        double total = 0.3 * skeleton + 0.4 * dice + 0.2 * focal + 0.1 * conn;
        if (isnan(total) || isinf(total)) total = dice;

        float f = (float)total;
        for (int j = 0; j < out_size; j++) out[j] = f;
    }
}

extern "C" void kernel_launch(void* const* d_in, const int* in_sizes, int n_in,
                              void* d_out, int out_size) {
    (void)in_sizes; (void)n_in;
    const float* pred = (const float*)d_in[0];
    const float* target = (const float*)d_in[1];
    float* out = (float*)d_out;

    k_init<<<dim3(GRIDX, GRIDY, NB), dim3(32, 8)>>>(pred, target);
    for (int i = 1; i <= 10; i++)
        k_iter<<<NW / 4 / 256, 256>>>(i);
    k_final<<<FBLK, 256>>>();
    k_finish<<<1, 256>>>(out, out_size);
}

// round 3
// speedup vs baseline: 2.8361x; 1.2679x over previous
#include <cuda_runtime.h>
#include <math.h>

#define IMW 1024
#define IMH 1024
#define NB  16
#define NPIX (NB * IMH * IMW)          // 16,777,216
#define WPR  (IMW / 32)                // 32 words per row
#define NWPI (IMH * WPR)               // 32768 words per image
#define NW   (NB * NWPI)               // 524,288 words per mask
#define GRIDX (IMW / 32)
#define GRIDY (IMH / 32)
#define NBLK0 (NB * GRIDX * GRIDY)     // 16384 init blocks
#define FBLK  (NW / 256)               // 2048 final blocks

// bitmaps: [mask(0=pred,1=target)][iteration 0..10][word]
__device__ unsigned g_bm[2][11][NW];
__device__ unsigned g_psum[22];          // popcounts per mask/iter
__device__ double g_part0[NBLK0 * 6];    // sum_p, sum_t, sum_pt, focal, conn, n_water
__device__ double g_part1[FBLK * 3];     // sumPskel, sumTskel, inter_s

__device__ __forceinline__ double warp_sum_d(double v) {
#pragma unroll
    for (int o = 16; o > 0; o >>= 1) v += __shfl_down_sync(0xffffffffu, v, o);
    return v;
}
__device__ __forceinline__ unsigned warp_sum_u(unsigned v) {
#pragma unroll
    for (int o = 16; o > 0; o >>= 1) v += __shfl_down_sync(0xffffffffu, v, o);
    return v;
}

// ---------------------------------------------------------------------------
// k_init: sigmoid (accurate — binarization must stay bit-identical), pointwise
// losses with single fast-log focal, separable 3x3 box conv, emit bitmaps.
// Block (32,8): thread (x,y) handles column x, tile rows 4y..4y+3.
// ---------------------------------------------------------------------------
__global__ void k_init(const float* __restrict__ pred, const float* __restrict__ target) {
    __shared__ float sp[34][34];
    __shared__ float st[34][34];
    __shared__ float hp[34][32];   // horizontal 3-sums, row i = tile row i-1
    __shared__ float ht[34][32];

    const int tx = threadIdx.x;
    const int ty = threadIdx.y;
    const int tid = ty * 32 + tx;
    const int gx0 = blockIdx.x * 32 - 1;
    const int gy0 = blockIdx.y * 32 - 1;
    const size_t ib = (size_t)blockIdx.z * (size_t)(IMH * IMW);

    if (blockIdx.x == 0 && blockIdx.y == 0 && blockIdx.z == 0 && tid < 22)
        g_psum[tid] = 0u;

    for (int idx = tid; idx < 34 * 34; idx += 256) {
        int ly = idx / 34, lx = idx - ly * 34;
        int gy = gy0 + ly, gx = gx0 + lx;
        float pv = 0.f, tv = 0.f;
        if ((unsigned)gy < (unsigned)IMH && (unsigned)gx < (unsigned)IMW) {
            size_t g = ib + (size_t)gy * IMW + (size_t)gx;
            float x = pred[g];
            pv = 1.0f / (1.0f + expf(-x));   // accurate: binarization depends on this
            tv = target[g];
        }
        sp[ly][lx] = pv;
        st[ly][lx] = tv;
    }
    __syncthreads();

    // horizontal 3-sums (34 rows x 32 cols)
    for (int idx = tid; idx < 34 * 32; idx += 256) {
        int r = idx >> 5, c = idx & 31;
        hp[r][c] = sp[r][c] + sp[r][c + 1] + sp[r][c + 2];
        ht[r][c] = st[r][c] + st[r][c + 1] + st[r][c + 2];
    }
    __syncthreads();

    float hpr[6], htr[6];
#pragma unroll
    for (int i = 0; i < 6; i++) {
        hpr[i] = hp[4 * ty + i][tx];
        htr[i] = ht[4 * ty + i][tx];
    }

    float a_sum_p = 0.f, a_sum_t = 0.f, a_sum_pt = 0.f, a_focal = 0.f, a_conn = 0.f, a_nw = 0.f;

#pragma unroll
    for (int r = 0; r < 4; r++) {
        const int lrow = 4 * ty + r;           // tile row
        float p = sp[lrow + 1][tx + 1];
        float t = st[lrow + 1][tx + 1];

        a_sum_p += p;
        a_sum_t += t;
        a_sum_pt += p * t;

        // focal: alpha_t * (1-pt)^2 * (-log pt), pt = t ? pc : 1-pc
        float pc = fminf(fmaxf(p, 1e-6f), 1.0f - 1e-6f);
        bool water = (t > 0.5f);
        float pt_ = water ? pc : (1.0f - pc);
        float at = water ? 0.25f : 0.75f;
        float om = 1.0f - pt_;
        a_focal += at * om * om * (-__logf(pt_));

        // connectivity: vertical 3-sum of horizontal 3-sums
        if (water) {
            float boxp = hpr[r] + hpr[r + 1] + hpr[r + 2];
            float boxt = htr[r] + htr[r + 1] + htr[r + 2];
            float d = (boxp - boxt) * (1.0f / 9.0f);
            a_conn += d * d;
            a_nw += 1.0f;
        }

        unsigned bp = __ballot_sync(0xffffffffu, p > 0.5f);
        unsigned bt = __ballot_sync(0xffffffffu, water);
        if (tx == 0) {
            int gy = blockIdx.y * 32 + lrow;
            int w = (int)blockIdx.z * NWPI + gy * WPR + (int)blockIdx.x;
            g_bm[0][0][w] = bp;
            g_bm[1][0][w] = bt;
        }
    }

    __shared__ double red[8][6];
    double vals[6] = { (double)a_sum_p, (double)a_sum_t, (double)a_sum_pt,
                       (double)a_focal, (double)a_conn, (double)a_nw };
    int lane = tid & 31, wid = tid >> 5;
#pragma unroll
    for (int k = 0; k < 6; k++) {
        double v = warp_sum_d(vals[k]);
        if (lane == 0) red[wid][k] = v;
    }
    __syncthreads();
    if (tid == 0) {
        int bid = ((int)blockIdx.z * GRIDY + (int)blockIdx.y) * GRIDX + (int)blockIdx.x;
#pragma unroll
        for (int k = 0; k < 6; k++) {
            double s = 0;
            for (int w2 = 0; w2 < 8; w2++) s += red[w2][k];
            g_part0[bid * 6 + k] = s;
        }
    }
}

// ---------------------------------------------------------------------------
// k_iter(i): bitmap skeleton step, state i-1 -> state i, one mask per blockIdx.y.
//   i odd : out = erode9(b); i even: out = (3x3 popcount >= 5)
// Early-exit: scan g_psum history; if this mask already converged, skip.
// Each thread: 4 consecutive words of one row.
// ---------------------------------------------------------------------------
__global__ void k_iter(int iter) {
    const int m = blockIdx.y;

    if (iter >= 3) {
        unsigned prev = g_psum[m * 11 + 1] << 1;
        for (int j = 2; j < iter; j++) {
            unsigned cur = g_psum[m * 11 + j] << (j & 1);
            if (cur == prev) return;       // converged at iter j: freeze
            prev = cur;
        }
    }

    const int t4 = blockIdx.x * blockDim.x + threadIdx.x;  // 0..NW/4-1
    const int w0 = t4 * 4;
    const int img = w0 >> 15;
    const int row = (w0 >> 5) & 1023;
    const int cb = w0 & 31;
    const size_t base = (size_t)img * NWPI + (size_t)row * WPR;
    const bool odd = (iter & 1) != 0;

    const unsigned* __restrict__ in = g_bm[m][iter - 1];
    unsigned* __restrict__ out = g_bm[m][iter];

    unsigned u[6], md[6], d[6];
#pragma unroll
    for (int i = 0; i < 6; i++) {
        int c = cb - 1 + i;
        bool cok = (unsigned)c < 32u;
        u[i]  = (cok && row > 0)    ? in[base - WPR + c] : 0u;
        md[i] = (cok)               ? in[base + c]       : 0u;
        d[i]  = (cok && row < 1023) ? in[base + WPR + c] : 0u;
    }

    unsigned pop = 0;
    if (odd) {
        unsigned va[6];
#pragma unroll
        for (int i = 0; i < 6; i++) va[i] = u[i] & md[i] & d[i];
#pragma unroll
        for (int j = 0; j < 4; j++) {
            unsigned c = va[j + 1];
            unsigned o = c & ((c << 1) | (va[j] >> 31)) & ((c >> 1) | (va[j + 2] << 31));
            out[base + cb + j] = o;
            pop += __popc(o);
        }
    } else {
        unsigned s0[6], s1[6];
#pragma unroll
        for (int i = 0; i < 6; i++) {
            s0[i] = u[i] ^ md[i] ^ d[i];
            s1[i] = (u[i] & md[i]) | (d[i] & (u[i] | md[i]));
        }
#pragma unroll
        for (int j = 0; j < 4; j++) {
            unsigned c0 = s0[j + 1], c1 = s1[j + 1];
            unsigned w0b = (c0 << 1) | (s0[j] >> 31);
            unsigned w1b = (c1 << 1) | (s1[j] >> 31);
            unsigned e0 = (c0 >> 1) | (s0[j + 2] << 31);
            unsigned e1 = (c1 >> 1) | (s1[j + 2] << 31);
            unsigned t0 = w0b ^ c0, car0 = w0b & c0;
            unsigned x = w1b ^ c1;
            unsigned t1 = x ^ car0;
            unsigned car1 = (w1b & c1) | (car0 & x);
            unsigned u0 = t0 ^ e0, k0 = t0 & e0;
            unsigned y = t1 ^ e1;
            unsigned u1 = y ^ k0;
            unsigned k1 = (t1 & e1) | (k0 & y);
            unsigned u2 = car1 ^ k1;
            unsigned u3 = car1 & k1;
            unsigned o = u3 | (u2 & (u1 | u0));  // total >= 5
            out[base + cb + j] = o;
            pop += __popc(o);
        }
    }

    __shared__ unsigned red[8];
    int lane = threadIdx.x & 31, wid = threadIdx.x >> 5;
    unsigned v = warp_sum_u(pop);
    if (lane == 0) red[wid] = v;
    __syncthreads();
    if (threadIdx.x == 0) {
        unsigned s = 0;
        for (int w2 = 0; w2 < 8; w2++) s += red[w2];
        atomicAdd(&g_psum[m * 11 + iter], s);
    }
}

// ---------------------------------------------------------------------------
// k_final: snapshot selection + Sobel LUT + skeleton-dice partials.
// ---------------------------------------------------------------------------
__global__ void k_final() {
    __shared__ float lut[512];
    __shared__ int s_sel[2];
    const int tid = threadIdx.x;

    for (int i = tid; i < 512; i += 256) {
        int n0 = i & 1, n1 = (i >> 1) & 1, n2 = (i >> 2) & 1;
        int n3 = (i >> 3) & 1, n5 = (i >> 5) & 1;
        int n6 = (i >> 6) & 1, n7 = (i >> 7) & 1, n8 = (i >> 8) & 1;
        int gx = (n2 + 2 * n5 + n8) - (n0 + 2 * n3 + n6);
        int gy = (n6 + 2 * n7 + n8) - (n0 + 2 * n1 + n2);
        lut[i] = 0.5f * sqrtf((float)(gx * gx + gy * gy) + 1e-8f);
    }
    if (tid == 0) {
#pragma unroll
        for (int m = 0; m < 2; m++) {
            unsigned prev = g_psum[m * 11 + 1] << 1;
            int sel = 10;
            for (int i = 2; i <= 10; i++) {
                unsigned cur = g_psum[m * 11 + i] << (i & 1);
                if (cur == prev) { sel = i; break; }
                prev = cur;
            }
            s_sel[m] = sel;
        }
    }
    __syncthreads();

    const int selP = s_sel[0], selT = s_sel[1];
    const float scP = (selP & 1) ? 2.0f : 1.0f;
    const float scT = (selT & 1) ? 2.0f : 1.0f;

    const int w = blockIdx.x * 256 + tid;
    const int img = w >> 15;
    const int row = (w >> 5) & 1023;
    const int col = w & 31;
    const size_t base = (size_t)img * NWPI + (size_t)row * WPR + col;
    const bool hasU = row > 0, hasD = row < 1023, hasL = col > 0, hasR = col < 31;

    unsigned long long e[2][3];
#pragma unroll
    for (int m = 0; m < 2; m++) {
        const unsigned* __restrict__ b = g_bm[m][0];
        unsigned U  = hasU ? b[base - WPR] : 0u;
        unsigned UL = (hasU && hasL) ? b[base - WPR - 1] : 0u;
        unsigned UR = (hasU && hasR) ? b[base - WPR + 1] : 0u;
        unsigned M  = b[base];
        unsigned L  = hasL ? b[base - 1] : 0u;
        unsigned R  = hasR ? b[base + 1] : 0u;
        unsigned D  = hasD ? b[base + WPR] : 0u;
        unsigned DL = (hasD && hasL) ? b[base + WPR - 1] : 0u;
        unsigned DR = (hasD && hasR) ? b[base + WPR + 1] : 0u;
        e[m][0] = ((unsigned long long)(UR & 1u) << 33) | ((unsigned long long)U << 1) | (UL >> 31);
        e[m][1] = ((unsigned long long)(R & 1u) << 33) | ((unsigned long long)M << 1) | (L >> 31);
        e[m][2] = ((unsigned long long)(DR & 1u) << 33) | ((unsigned long long)D << 1) | (DL >> 31);
    }
    const unsigned skP = g_bm[0][selP][base];
    const unsigned skT = g_bm[1][selT][base];

    float aPs = 0.f, aTs = 0.f, aI = 0.f;
#pragma unroll 8
    for (int k = 0; k < 32; k++) {
        unsigned idxP = ((unsigned)(e[0][0] >> k) & 7u) | (((unsigned)(e[0][1] >> k) & 7u) << 3)
                      | (((unsigned)(e[0][2] >> k) & 7u) << 6);
        unsigned idxT = ((unsigned)(e[1][0] >> k) & 7u) | (((unsigned)(e[1][1] >> k) & 7u) << 3)
                      | (((unsigned)(e[1][2] >> k) & 7u) << 6);
        float vP = fminf((((skP >> k) & 1u) ? scP : 0.f) + lut[idxP], 1.0f);
        float vT = fminf((((skT >> k) & 1u) ? scT : 0.f) + lut[idxT], 1.0f);
        aPs += vP;
        aTs += vT;
        aI += vP * vT;
    }

    __shared__ double red[8][3];
    double vals[3] = { (double)aPs, (double)aTs, (double)aI };
    int lane = tid & 31, wid = tid >> 5;
#pragma unroll
    for (int k = 0; k < 3; k++) {
        double v = warp_sum_d(vals[k]);
        if (lane == 0) red[wid][k] = v;
    }
    __syncthreads();
    if (tid == 0) {
#pragma unroll
        for (int k = 0; k < 3; k++) {
            double s = 0;
            for (int w2 = 0; w2 < 8; w2++) s += red[w2][k];
            g_part1[blockIdx.x * 3 + k] = s;
        }
    }
}

// ---------------------------------------------------------------------------
// k_finish: deterministic fixed-order reduction + loss combine.
// ---------------------------------------------------------------------------
__global__ void k_finish(float* __restrict__ out, int out_size) {
    const int tid = threadIdx.x;  // 256 threads
    double acc[9];
#pragma unroll
    for (int k = 0; k < 9; k++) acc[k] = 0.0;

    for (int i = tid; i < NBLK0; i += 256)
#pragma unroll
        for (int k = 0; k < 6; k++) acc[k] += g_part0[i * 6 + k];
    for (int i = tid; i < FBLK; i += 256)
#pragma unroll
        for (int k = 0; k < 3; k++) acc[6 + k] += g_part1[i * 3 + k];

    __shared__ double red[8][9];
    int lane = tid & 31, wid = tid >> 5;
#pragma unroll
    for (int k = 0; k < 9; k++) {
        double v = warp_sum_d(acc[k]);
        if (lane == 0) red[wid][k] = v;
    }
    __syncthreads();
    if (tid == 0) {
        double A[9];
#pragma unroll
        for (int k = 0; k < 9; k++) {
            double s = 0;
            for (int w2 = 0; w2 < 8; w2++) s += red[w2][k];
            A[k] = s;
        }
        double sum_p = A[0], sum_t = A[1], sum_pt = A[2];
        double focal_sum = A[3], conn_num = A[4], nw = A[5];
        double sPs = A[6], sTs = A[7], inter_s = A[8];

        double skeleton = 1.0 - (2.0 * inter_s + 1.0) / (sPs + sTs + 1.0);
        double dice = 1.0 - (2.0 * sum_pt + 1.0) / (sum_p + sum_t + 1.0);
        double focal = focal_sum / (double)NPIX;
        focal = fmin(fmax(focal, 0.0), 10.0);
        double conn = (nw == 0.0) ? 0.0 : conn_num / fmax(nw, 1.0);

        double total = 0.3 * skeleton + 0.4 * dice + 0.2 * focal + 0.1 * conn;
        if (isnan(total) || isinf(total)) total = dice;

        float f = (float)total;
        for (int j = 0; j < out_size; j++) out[j] = f;
    }
}

extern "C" void kernel_launch(void* const* d_in, const int* in_sizes, int n_in,
                              void* d_out, int out_size) {
    (void)in_sizes; (void)n_in;
    const float* pred = (const float*)d_in[0];
    const float* target = (const float*)d_in[1];
    float* out = (float*)d_out;

    k_init<<<dim3(GRIDX, GRIDY, NB), dim3(32, 8)>>>(pred, target);
    for (int i = 1; i <= 10; i++)
        k_iter<<<dim3(NW / 4 / 256, 2), 256>>>(i);
    k_final<<<FBLK, 256>>>();
    k_finish<<<1, 256>>>(out, out_size);
}

// round 4
// speedup vs baseline: 4.5626x; 1.6088x over previous
#include <cuda_runtime.h>
#include <math.h>

#define IMW 1024
#define IMH 1024
#define NB  16
#define NPIX (NB * IMH * IMW)          // 16,777,216
#define WPR  (IMW / 32)                // 32 words per row
#define NWPI (IMH * WPR)               // 32768 words per image
#define NW   (NB * NWPI)               // 524,288 words per mask
#define NITEMS (NW / 4)                // 131072 4-word items per mask
#define GRIDX (IMW / 32)
#define GRIDY (IMH / 32)
#define NBLK0 (NB * GRIDX * GRIDY)     // 16384 init blocks
#define NBLKP 512                      // persistent blocks (co-resident: <=4/SM)
#define NTHP  256
#define GT    (NBLKP * NTHP)           // 131072 threads

__device__ __align__(16) unsigned g_bm[2][11][NW];
__device__ unsigned g_psum[22];
__device__ double g_part0[NBLK0 * 6];
__device__ double g_p0red[NBLKP * 6];
__device__ double g_part1[NBLKP * 3];
__device__ unsigned g_bar_arrive = 0;
__device__ volatile unsigned g_bar_gen = 0;

__device__ __forceinline__ double warp_sum_d(double v) {
#pragma unroll
    for (int o = 16; o > 0; o >>= 1) v += __shfl_down_sync(0xffffffffu, v, o);
    return v;
}
__device__ __forceinline__ unsigned warp_sum_u(unsigned v) {
#pragma unroll
    for (int o = 16; o > 0; o >>= 1) v += __shfl_down_sync(0xffffffffu, v, o);
    return v;
}

__device__ __forceinline__ void grid_sync() {
    __syncthreads();
    if (threadIdx.x == 0) {
        unsigned gen = g_bar_gen;
        __threadfence();
        if (atomicAdd(&g_bar_arrive, 1u) == NBLKP - 1) {
            g_bar_arrive = 0u;
            __threadfence();
            g_bar_gen = gen + 1u;
        } else {
            while (g_bar_gen == gen) __nanosleep(64);
        }
        __threadfence();
    }
    __syncthreads();
}

__device__ __forceinline__ void load_row6(const unsigned* __restrict__ p, long widx,
                                          int cb, bool ok, unsigned w[6]) {
    if (ok) {
        const unsigned* r = p + widx;
        w[0] = (cb > 0) ? r[cb - 1] : 0u;
        uint4 c = *reinterpret_cast<const uint4*>(r + cb);
        w[1] = c.x; w[2] = c.y; w[3] = c.z; w[4] = c.w;
        w[5] = (cb < 28) ? r[cb + 4] : 0u;
    } else {
        w[0] = w[1] = w[2] = w[3] = w[4] = w[5] = 0u;
    }
}

// ---------------------------------------------------------------------------
// k_init
// ---------------------------------------------------------------------------
__global__ void k_init(const float* __restrict__ pred, const float* __restrict__ target) {
    __shared__ float sp[34][34];   // sign encodes (x>0); |value| = sigmoid(x)
    __shared__ float st[34][34];
    __shared__ float hp[34][32];
    __shared__ float ht[34][32];

    const int tx = threadIdx.x;
    const int ty = threadIdx.y;
    const int tid = ty * 32 + tx;
    const int gx0 = blockIdx.x * 32 - 1;
    const int gy0 = blockIdx.y * 32 - 1;
    const size_t ib = (size_t)blockIdx.z * (size_t)(IMH * IMW);

    if (blockIdx.x == 0 && blockIdx.y == 0 && blockIdx.z == 0 && tid < 22)
        g_psum[tid] = 0u;

    for (int idx = tid; idx < 34 * 34; idx += 256) {
        int ly = idx / 34, lx = idx - ly * 34;
        int gy = gy0 + ly, gx = gx0 + lx;
        float pv = 0.f, tv = 0.f;
        if ((unsigned)gy < (unsigned)IMH && (unsigned)gx < (unsigned)IMW) {
            size_t g = ib + (size_t)gy * IMW + (size_t)gx;
            float x = pred[g];
            float p = __fdividef(1.0f, 1.0f + __expf(-x));
            pv = (x > 0.0f) ? p : -p;
            tv = target[g];
        }
        sp[ly][lx] = pv;
        st[ly][lx] = tv;
    }
    __syncthreads();

    for (int idx = tid; idx < 34 * 32; idx += 256) {
        int r = idx >> 5, c = idx & 31;
        hp[r][c] = fabsf(sp[r][c]) + fabsf(sp[r][c + 1]) + fabsf(sp[r][c + 2]);
        ht[r][c] = st[r][c] + st[r][c + 1] + st[r][c + 2];
    }
    __syncthreads();

    float hpr[6], htr[6];
#pragma unroll
    for (int i = 0; i < 6; i++) {
        hpr[i] = hp[4 * ty + i][tx];
        htr[i] = ht[4 * ty + i][tx];
    }

    float a_sum_p = 0.f, a_sum_t = 0.f, a_sum_pt = 0.f, a_focal = 0.f, a_conn = 0.f, a_nw = 0.f;

#pragma unroll
    for (int r = 0; r < 4; r++) {
        const int lrow = 4 * ty + r;
        float sv = sp[lrow + 1][tx + 1];
        float p = fabsf(sv);
        float t = st[lrow + 1][tx + 1];

        a_sum_p += p;
        a_sum_t += t;
        a_sum_pt += p * t;

        float pc = fminf(fmaxf(p, 1e-6f), 1.0f - 1e-6f);
        bool water = (t > 0.5f);
        float pt_ = water ? pc : (1.0f - pc);
        float at = water ? 0.25f : 0.75f;
        float om = 1.0f - pt_;
        a_focal += at * om * om * (-__logf(pt_));

        if (water) {
            float boxp = hpr[r] + hpr[r + 1] + hpr[r + 2];
            float boxt = htr[r] + htr[r + 1] + htr[r + 2];
            float d = (boxp - boxt) * (1.0f / 9.0f);
            a_conn += d * d;
            a_nw += 1.0f;
        }

        unsigned bp = __ballot_sync(0xffffffffu, sv > 0.0f);
        unsigned bt = __ballot_sync(0xffffffffu, water);
        if (tx == 0) {
            int gy = blockIdx.y * 32 + lrow;
            int w = (int)blockIdx.z * NWPI + gy * WPR + (int)blockIdx.x;
            g_bm[0][0][w] = bp;
            g_bm[1][0][w] = bt;
        }
    }

    __shared__ double red[8][6];
    double vals[6] = { (double)a_sum_p, (double)a_sum_t, (double)a_sum_pt,
                       (double)a_focal, (double)a_conn, (double)a_nw };
    int lane = tid & 31, wid = tid >> 5;
#pragma unroll
    for (int k = 0; k < 6; k++) {
        double v = warp_sum_d(vals[k]);
        if (lane == 0) red[wid][k] = v;
    }
    __syncthreads();
    if (tid == 0) {
        int bid = ((int)blockIdx.z * GRIDY + (int)blockIdx.y) * GRIDX + (int)blockIdx.x;
#pragma unroll
        for (int k = 0; k < 6; k++) {
            double s = 0;
            for (int w2 = 0; w2 < 8; w2++) s += red[w2][k];
            g_part0[bid * 6 + k] = s;
        }
    }
}

// ---------------------------------------------------------------------------
// bit-sliced Sobel classification helpers
// ---------------------------------------------------------------------------
__device__ __forceinline__ void bits3(unsigned x, unsigned y, unsigned z,
                                      unsigned& o0, unsigned& o1, unsigned& o2) {
    unsigned s = x ^ z, c = x & z;
    o0 = s; o1 = c ^ y; o2 = c & y;
}
__device__ __forceinline__ unsigned eq3(unsigned a0, unsigned a1, unsigned a2,
                                        unsigned b0, unsigned b1, unsigned b2) {
    return ~((a0 ^ b0) | (a1 ^ b1) | (a2 ^ b2));
}
__device__ __forceinline__ void inc3(unsigned b0, unsigned b1, unsigned b2,
                                     unsigned& o0, unsigned& o1, unsigned& o2) {
    o0 = ~b0; o1 = b1 ^ b0; o2 = b2 ^ (b1 & b0);
}

__device__ __forceinline__ void class_masks(const unsigned u[6], const unsigned mw[6],
                                            const unsigned d[6], unsigned S, int j,
                                            unsigned M[4]) {
    const int idx = j + 1;
    unsigned CU = u[idx], CM = mw[idx], CD = d[idx];
    unsigned LU = (CU << 1) | (u[idx - 1] >> 31);
    unsigned RU = (CU >> 1) | (u[idx + 1] << 31);
    unsigned LM = (CM << 1) | (mw[idx - 1] >> 31);
    unsigned RM = (CM >> 1) | (mw[idx + 1] << 31);
    unsigned LD = (CD << 1) | (d[idx - 1] >> 31);
    unsigned RD = (CD >> 1) | (d[idx + 1] << 31);

    unsigned a0, a1, a2, b0, b1, b2, i0, i1, i2;
    bits3(RU, RM, RD, a0, a1, a2);
    bits3(LU, LM, LD, b0, b1, b2);
    unsigned gx0 = eq3(a0, a1, a2, b0, b1, b2);
    inc3(b0, b1, b2, i0, i1, i2);
    unsigned gx1 = eq3(a0, a1, a2, i0, i1, i2);
    inc3(a0, a1, a2, i0, i1, i2);
    gx1 |= eq3(i0, i1, i2, b0, b1, b2);

    bits3(LD, CD, RD, a0, a1, a2);
    bits3(LU, CU, RU, b0, b1, b2);
    unsigned gy0 = eq3(a0, a1, a2, b0, b1, b2);
    inc3(b0, b1, b2, i0, i1, i2);
    unsigned gy1 = eq3(a0, a1, a2, i0, i1, i2);
    inc3(a0, a1, a2, i0, i1, i2);
    gy1 |= eq3(i0, i1, i2, b0, b1, b2);

    unsigned B0 = gx0 & gy0;
    unsigned B1 = (gx0 & gy1) | (gx1 & gy0);
    unsigned B2 = gx1 & gy1;
    unsigned nS = ~S;
    M[0] = B0 & nS;
    M[1] = B1 & nS;
    M[2] = B2 & nS;
    M[3] = (~(B0 | B1 | B2)) | S;
}

// ---------------------------------------------------------------------------
// k_persist: skeleton loop + final pass + reductions in one launch
// ---------------------------------------------------------------------------
__global__ void __launch_bounds__(NTHP, 4) k_persist(float* __restrict__ out, int out_size) {
    const int tid = threadIdx.x;
    const int bid = blockIdx.x;
    const int gtid = bid * NTHP + tid;
    const int lane = tid & 31, wid = tid >> 5;

    __shared__ unsigned s_ps[22];
    __shared__ int s_flag[2];
    __shared__ int s_sel[2];
    __shared__ unsigned redP[8], redT[8];

    for (int iter = 1; iter <= 10; iter++) {
        if (tid < 22) s_ps[tid] = g_psum[tid];
        __syncthreads();
        if (tid == 0) {
#pragma unroll
            for (int m = 0; m < 2; m++) {
                int done = 0;
                if (iter >= 3) {
                    unsigned prev = s_ps[m * 11 + 1] << 1;
                    for (int j = 2; j < iter; j++) {
                        unsigned cur = s_ps[m * 11 + j] << (j & 1);
                        if (cur == prev) { done = 1; break; }
                        prev = cur;
                    }
                }
                s_flag[m] = done;
            }
        }
        __syncthreads();
        const int doneP = s_flag[0], doneT = s_flag[1];
        if (doneP && doneT) break;

        const bool oddIt = (iter & 1) != 0;
        unsigned popm0 = 0, popm1 = 0;

        for (int it = gtid; it < 2 * NITEMS; it += GT) {
            const int m = it >> 17;
            if (m ? doneT : doneP) continue;
            const int i4 = it & (NITEMS - 1);
            const int w0 = i4 * 4;
            const int img = w0 >> 15;
            const int row = (w0 >> 5) & 1023;
            const int cb = w0 & 31;
            const long base = (long)img * NWPI + (long)row * WPR;
            const unsigned* __restrict__ in = g_bm[m][iter - 1];
            unsigned* __restrict__ outp = g_bm[m][iter];

            unsigned u[6], md[6], d[6];
            load_row6(in, base - WPR, cb, row > 0, u);
            load_row6(in, base, cb, true, md);
            load_row6(in, base + WPR, cb, row < 1023, d);

            unsigned o4[4];
            unsigned pop = 0;
            if (oddIt) {
                unsigned va[6];
#pragma unroll
                for (int i = 0; i < 6; i++) va[i] = u[i] & md[i] & d[i];
#pragma unroll
                for (int j = 0; j < 4; j++) {
                    unsigned c = va[j + 1];
                    unsigned o = c & ((c << 1) | (va[j] >> 31)) & ((c >> 1) | (va[j + 2] << 31));
                    o4[j] = o;
                    pop += __popc(o);
                }
            } else {
                unsigned s0[6], s1[6];
#pragma unroll
                for (int i = 0; i < 6; i++) {
                    s0[i] = u[i] ^ md[i] ^ d[i];
                    s1[i] = (u[i] & md[i]) | (d[i] & (u[i] | md[i]));
                }
#pragma unroll
                for (int j = 0; j < 4; j++) {
                    unsigned c0 = s0[j + 1], c1 = s1[j + 1];
                    unsigned w0b = (c0 << 1) | (s0[j] >> 31);
                    unsigned w1b = (c1 << 1) | (s1[j] >> 31);
                    unsigned e0 = (c0 >> 1) | (s0[j + 2] << 31);
                    unsigned e1 = (c1 >> 1) | (s1[j + 2] << 31);
                    unsigned t0 = w0b ^ c0, car0 = w0b & c0;
                    unsigned x = w1b ^ c1;
                    unsigned t1 = x ^ car0;
                    unsigned car1 = (w1b & c1) | (car0 & x);
                    unsigned u0 = t0 ^ e0, k0 = t0 & e0;
                    unsigned y = t1 ^ e1;
                    unsigned u1 = y ^ k0;
                    unsigned k1 = (t1 & e1) | (k0 & y);
                    unsigned u2 = car1 ^ k1;
                    unsigned u3 = car1 & k1;
                    unsigned o = u3 | (u2 & (u1 | u0));
                    o4[j] = o;
                    pop += __popc(o);
                }
            }
            *reinterpret_cast<uint4*>(outp + base + cb) = make_uint4(o4[0], o4[1], o4[2], o4[3]);
            if (m) popm1 += pop; else popm0 += pop;
        }

        unsigned vp = warp_sum_u(popm0);
        unsigned vt = warp_sum_u(popm1);
        if (lane == 0) { redP[wid] = vp; redT[wid] = vt; }
        __syncthreads();
        if (tid == 0) {
            unsigned sP = 0, sT = 0;
            for (int w2 = 0; w2 < 8; w2++) { sP += redP[w2]; sT += redT[w2]; }
            if (!doneP) atomicAdd(&g_psum[iter], sP);
            if (!doneT) atomicAdd(&g_psum[11 + iter], sT);
        }
        grid_sync();
    }

    if (tid < 22) s_ps[tid] = g_psum[tid];
    __syncthreads();
    if (tid == 0) {
#pragma unroll
        for (int m = 0; m < 2; m++) {
            unsigned prev = s_ps[m * 11 + 1] << 1;
            int sel = 10;
            for (int i = 2; i <= 10; i++) {
                unsigned cur = s_ps[m * 11 + i] << (i & 1);
                if (cur == prev) { sel = i; break; }
                prev = cur;
            }
            s_sel[m] = sel;
        }
    }
    __syncthreads();
    const int selP = s_sel[0], selT = s_sel[1];

    const float tb[4] = { 0.5f * sqrtf(1e-8f), 0.5f * sqrtf(1.0f + 1e-8f),
                          0.5f * sqrtf(2.0f + 1e-8f), 1.0f };

    float aPs = 0.f, aTs = 0.f, aI = 0.f;
    {
        const int i4 = gtid;
        const int w0 = i4 * 4;
        const int img = w0 >> 15;
        const int row = (w0 >> 5) & 1023;
        const int cb = w0 & 31;
        const long base = (long)img * NWPI + (long)row * WPR;

        unsigned MP[4][4];
        {
            const unsigned* __restrict__ b = g_bm[0][0];
            unsigned u[6], mw[6], d[6];
            load_row6(b, base - WPR, cb, row > 0, u);
            load_row6(b, base, cb, true, mw);
            load_row6(b, base + WPR, cb, row < 1023, d);
            uint4 sk = *reinterpret_cast<const uint4*>(g_bm[0][selP] + base + cb);
            unsigned skw[4] = { sk.x, sk.y, sk.z, sk.w };
#pragma unroll
            for (int j = 0; j < 4; j++)
                class_masks(u, mw, d, skw[j], j, MP[j]);
        }
        {
            const unsigned* __restrict__ b = g_bm[1][0];
            unsigned u[6], mw[6], d[6];
            load_row6(b, base - WPR, cb, row > 0, u);
            load_row6(b, base, cb, true, mw);
            load_row6(b, base + WPR, cb, row < 1023, d);
            uint4 sk = *reinterpret_cast<const uint4*>(g_bm[1][selT] + base + cb);
            unsigned skw[4] = { sk.x, sk.y, sk.z, sk.w };
#pragma unroll
            for (int j = 0; j < 4; j++) {
                unsigned MT[4];
                class_masks(u, mw, d, skw[j], j, MT);
#pragma unroll
                for (int i = 0; i < 4; i++) {
                    aPs += tb[i] * (float)__popc(MP[j][i]);
                    aTs += tb[i] * (float)__popc(MT[i]);
#pragma unroll
                    for (int k = 0; k < 4; k++)
                        aI += (tb[i] * tb[k]) * (float)__popc(MP[j][i] & MT[k]);
                }
            }
        }
    }

    __shared__ double redf[8][3];
    {
        double vals[3] = { (double)aPs, (double)aTs, (double)aI };
#pragma unroll
        for (int k = 0; k < 3; k++) {
            double v = warp_sum_d(vals[k]);
            if (lane == 0) redf[wid][k] = v;
        }
        __syncthreads();
        if (tid == 0) {
#pragma unroll
            for (int k = 0; k < 3; k++) {
                double s = 0;
                for (int w2 = 0; w2 < 8; w2++) s += redf[w2][k];
                g_part1[bid * 3 + k] = s;
            }
        }
    }

    if (tid < 32) {
        int r = bid * 32 + tid;
        double v[6];
#pragma unroll
        for (int k = 0; k < 6; k++) v[k] = g_part0[r * 6 + k];
#pragma unroll
        for (int k = 0; k < 6; k++) {
            double s = warp_sum_d(v[k]);
            if (tid == 0) g_p0red[bid * 6 + k] = s;
        }
    }

    grid_sync();

    if (bid == 0) {
        double acc[9];
#pragma unroll
        for (int k = 0; k < 9; k++) acc[k] = 0.0;
        for (int i = tid; i < NBLKP; i += NTHP) {
#pragma unroll
            for (int k = 0; k < 6; k++) acc[k] += g_p0red[i * 6 + k];
#pragma unroll
            for (int k = 0; k < 3; k++) acc[6 + k] += g_part1[i * 3 + k];
        }
        __shared__ double redz[8][9];
#pragma unroll
        for (int k = 0; k < 9; k++) {
            double v = warp_sum_d(acc[k]);
            if (lane == 0) redz[wid][k] = v;
        }
        __syncthreads();
        if (tid == 0) {
            double A[9];
#pragma unroll
            for (int k = 0; k < 9; k++) {
                double s = 0;
                for (int w2 = 0; w2 < 8; w2++) s += redz[w2][k];
                A[k] = s;
            }
            double sum_p = A[0], sum_t = A[1], sum_pt = A[2];
            double focal_sum = A[3], conn_num = A[4], nw = A[5];
            double sPs = A[6], sTs = A[7], inter_s = A[8];

            double skeleton = 1.0 - (2.0 * inter_s + 1.0) / (sPs + sTs + 1.0);
            double dice = 1.0 - (2.0 * sum_pt + 1.0) / (sum_p + sum_t + 1.0);
            double focal = focal_sum / (double)NPIX;
            focal = fmin(fmax(focal, 0.0), 10.0);
            double conn = (nw == 0.0) ? 0.0 : conn_num / fmax(nw, 1.0);

            double total = 0.3 * skeleton + 0.4 * dice + 0.2 * focal + 0.1 * conn;
            if (isnan(total) || isinf(total)) total = dice;

            float f = (float)total;
            for (int j = 0; j < out_size; j++) out[j] = f;
        }
    }
}

extern "C" void kernel_launch(void* const* d_in, const int* in_sizes, int n_in,
                              void* d_out, int out_size) {
    (void)in_sizes; (void)n_in;
    const float* pred = (const float*)d_in[0];
    const float* target = (const float*)d_in[1];
    float* out = (float*)d_out;

    k_init<<<dim3(GRIDX, GRIDY, NB), dim3(32, 8)>>>(pred, target);
    k_persist<<<NBLKP, NTHP>>>(out, out_size);
}